// round 1
// baseline (speedup 1.0000x reference)
#include <cuda_runtime.h>
#include <cuda_bf16.h>
#include <math.h>

// Problem constants (crossatt_76544907149890)
#define BB 32
#define LD 2048
#define LQ 512
#define DD 256

// GEMM tile config
#define BM 128
#define BN 128
#define BK 16
#define TM 8
#define TN 8
#define NTHREADS 256

// Scratch (device globals; no allocation allowed)
__device__ float g_colsum[BB * LD];  // sum over q of tanh -> alpha logits
__device__ float g_rowsum[BB * LQ];  // sum over t of tanh -> beta logits
__device__ float g_alpha[BB * LD];
__device__ float g_beta[BB * LQ];

__device__ __forceinline__ float fast_tanh(float x) {
    // accurate to ~1e-6 abs (uses __expf, rel err ~2^-22)
    float cx = fminf(fmaxf(x, -15.0f), 15.0f);
    float e = __expf(2.0f * cx);
    return (e - 1.0f) / (e + 1.0f);
}

__global__ void zero_scratch_kernel() {
    int i = blockIdx.x * blockDim.x + threadIdx.x;
    int n1 = BB * LD;
    int n2 = BB * LQ;
    if (i < n1) g_colsum[i] = 0.0f;
    if (i < n2) g_rowsum[i] = 0.0f;
}

// Fused tanh(Q K^T) with row/col sum reduction. Never materializes S.
// grid: (LD/BN, LQ/BM, B), block: 256
__global__ __launch_bounds__(NTHREADS)
void tanh_gemm_kernel(const float* __restrict__ Q, const float* __restrict__ Kd) {
    __shared__ float As[BK][BM + 4];
    __shared__ float Bs[BK][BN + 4];
    __shared__ float srow[BM];
    __shared__ float scol[BN];

    const int b  = blockIdx.z;
    const int m0 = blockIdx.y * BM;
    const int n0 = blockIdx.x * BN;
    const int tid = threadIdx.x;
    const int tx = tid & 15;
    const int ty = tid >> 4;

    const float* Qb = Q  + ((size_t)b * LQ + m0) * DD;
    const float* Kb = Kd + ((size_t)b * LD + n0) * DD;

    float acc[TM][TN];
#pragma unroll
    for (int i = 0; i < TM; ++i)
#pragma unroll
        for (int j = 0; j < TN; ++j) acc[i][j] = 0.0f;

    // global->smem load mapping: each thread loads 2 float4 per matrix per stage
    const int lr = tid >> 2;          // row 0..63
    const int lc = (tid & 3) * 4;     // k offset 0,4,8,12

    for (int k0 = 0; k0 < DD; k0 += BK) {
#pragma unroll
        for (int r = 0; r < 2; ++r) {
            int row = lr + r * 64;
            float4 va = *reinterpret_cast<const float4*>(Qb + (size_t)row * DD + k0 + lc);
            As[lc + 0][row] = va.x; As[lc + 1][row] = va.y;
            As[lc + 2][row] = va.z; As[lc + 3][row] = va.w;
            float4 vb = *reinterpret_cast<const float4*>(Kb + (size_t)row * DD + k0 + lc);
            Bs[lc + 0][row] = vb.x; Bs[lc + 1][row] = vb.y;
            Bs[lc + 2][row] = vb.z; Bs[lc + 3][row] = vb.w;
        }
        __syncthreads();

#pragma unroll
        for (int kk = 0; kk < BK; ++kk) {
            // split-tile: rows {ty*4..+3, 64+ty*4..+3}, cols {tx*4..+3, 64+tx*4..+3}
            float4 a0 = *reinterpret_cast<const float4*>(&As[kk][ty * 4]);
            float4 a1 = *reinterpret_cast<const float4*>(&As[kk][64 + ty * 4]);
            float4 b0 = *reinterpret_cast<const float4*>(&Bs[kk][tx * 4]);
            float4 b1 = *reinterpret_cast<const float4*>(&Bs[kk][64 + tx * 4]);
            float a[TM] = {a0.x, a0.y, a0.z, a0.w, a1.x, a1.y, a1.z, a1.w};
            float bv[TN] = {b0.x, b0.y, b0.z, b0.w, b1.x, b1.y, b1.z, b1.w};
#pragma unroll
            for (int i = 0; i < TM; ++i)
#pragma unroll
                for (int j = 0; j < TN; ++j)
                    acc[i][j] = fmaf(a[i], bv[j], acc[i][j]);
        }
        __syncthreads();
    }

    // tanh + per-thread partial reductions
    if (tid < BM) srow[tid] = 0.0f;
    if (tid < BN) scol[tid] = 0.0f;
    __syncthreads();

    float rsum[TM], csum[TN];
#pragma unroll
    for (int i = 0; i < TM; ++i) rsum[i] = 0.0f;
#pragma unroll
    for (int j = 0; j < TN; ++j) csum[j] = 0.0f;

#pragma unroll
    for (int i = 0; i < TM; ++i) {
#pragma unroll
        for (int j = 0; j < TN; ++j) {
            float v = fast_tanh(acc[i][j]);
            rsum[i] += v;
            csum[j] += v;
        }
    }

#pragma unroll
    for (int i = 0; i < TM; ++i) {
        int m = ty * 4 + (i & 3) + (i >> 2) * 64;
        atomicAdd(&srow[m], rsum[i]);
    }
#pragma unroll
    for (int j = 0; j < TN; ++j) {
        int n = tx * 4 + (j & 3) + (j >> 2) * 64;
        atomicAdd(&scol[n], csum[j]);
    }
    __syncthreads();

    if (tid < BM) atomicAdd(&g_rowsum[b * LQ + m0 + tid], srow[tid]);
    if (tid < BN) atomicAdd(&g_colsum[b * LD + n0 + tid], scol[tid]);
}

// Masked softmax with renormalization folded in: w_i = e^{x_i - max} * m_i / sum(e * m)
// grid: (2, B) -- x=0: alpha over LD with doc_mask; x=1: beta over LQ with q_mask
__global__ __launch_bounds__(256)
void softmax_kernel(const float* __restrict__ doc_mask, const float* __restrict__ q_mask) {
    __shared__ float red[256];
    const int side = blockIdx.x;
    const int b = blockIdx.y;
    const int tid = threadIdx.x;

    const float* logits = (side == 0) ? (g_colsum + b * LD) : (g_rowsum + b * LQ);
    const float* mask   = (side == 0) ? (doc_mask + b * LD) : (q_mask + b * LQ);
    float* outw         = (side == 0) ? (g_alpha + b * LD)  : (g_beta + b * LQ);
    const int n         = (side == 0) ? LD : LQ;

    // max
    float mx = -INFINITY;
    for (int i = tid; i < n; i += 256) mx = fmaxf(mx, logits[i]);
    red[tid] = mx;
    __syncthreads();
    for (int s = 128; s > 0; s >>= 1) {
        if (tid < s) red[tid] = fmaxf(red[tid], red[tid + s]);
        __syncthreads();
    }
    mx = red[0];
    __syncthreads();

    // exp * mask, accumulate sum
    float ssum = 0.0f;
    for (int i = tid; i < n; i += 256) {
        float e = __expf(logits[i] - mx) * mask[i];
        outw[i] = e;
        ssum += e;
    }
    red[tid] = ssum;
    __syncthreads();
    for (int s = 128; s > 0; s >>= 1) {
        if (tid < s) red[tid] += red[tid + s];
        __syncthreads();
    }
    float inv = 1.0f / red[0];
    __syncthreads();

    for (int i = tid; i < n; i += 256) outw[i] *= inv;
}

// Weighted pooling: out[b, 0:256] = sum_t doc[b,t,:]*alpha[b,t];
//                   out[b, 256:512] = sum_q query[b,q,:]*beta[b,q]
// grid: (8, B), block: 256 (one thread per d)
__global__ __launch_bounds__(256)
void pool_kernel(const float* __restrict__ doc, const float* __restrict__ query,
                 float* __restrict__ out) {
    const int chunk = blockIdx.x;  // 0..7
    const int b = blockIdx.y;
    const int d = threadIdx.x;

    const int tpc = LD / 8;  // 256 doc rows per chunk
    const int qpc = LQ / 8;  // 64 query rows per chunk

    float accD = 0.0f;
    const float* dbase = doc + ((size_t)b * LD + chunk * tpc) * DD;
    const float* abase = g_alpha + b * LD + chunk * tpc;
    for (int t = 0; t < tpc; ++t)
        accD = fmaf(dbase[(size_t)t * DD + d], __ldg(&abase[t]), accD);

    float accQ = 0.0f;
    const float* qbase = query + ((size_t)b * LQ + chunk * qpc) * DD;
    const float* bbase = g_beta + b * LQ + chunk * qpc;
    for (int q = 0; q < qpc; ++q)
        accQ = fmaf(qbase[(size_t)q * DD + d], __ldg(&bbase[q]), accQ);

    atomicAdd(&out[b * (2 * DD) + d], accD);
    atomicAdd(&out[b * (2 * DD) + DD + d], accQ);
}

extern "C" void kernel_launch(void* const* d_in, const int* in_sizes, int n_in,
                              void* d_out, int out_size) {
    const float* doc      = (const float*)d_in[0];  // [32,2048,256]
    const float* query    = (const float*)d_in[1];  // [32,512,256]
    const float* doc_mask = (const float*)d_in[2];  // [32,2048]
    const float* q_mask   = (const float*)d_in[3];  // [32,512]
    float* out = (float*)d_out;                     // [32,512]

    // 1. zero scratch logit accumulators
    {
        int n = BB * LD;  // largest
        zero_scratch_kernel<<<(n + 1023) / 1024, 1024>>>();
    }
    // 2. zero output (pool kernel uses atomics)
    cudaMemsetAsync(d_out, 0, (size_t)out_size * sizeof(float));

    // 3. fused tanh-GEMM with row/col reduction
    {
        dim3 grid(LD / BN, LQ / BM, BB);
        tanh_gemm_kernel<<<grid, NTHREADS>>>(query, doc);
    }
    // 4. masked softmaxes
    {
        dim3 grid(2, BB);
        softmax_kernel<<<grid, 256>>>(doc_mask, q_mask);
    }
    // 5. weighted pooling
    {
        dim3 grid(8, BB);
        pool_kernel<<<grid, 256>>>(doc, query, out);
    }
}

// round 9
// speedup vs baseline: 1.1552x; 1.1552x over previous
#include <cuda_runtime.h>
#include <cuda_fp16.h>
#include <cstdint>
#include <math.h>

// Problem constants (crossatt_76544907149890)
#define BB 32
#define LD 2048
#define LQ 512
#define DD 256

// GEMM config
#define BM 128
#define BN 128
#define BK 32
#define NTHREADS 256
#define ROWP 40                 // padded row stride in halves (80B, conflict-free)
#define TILE_BYTES (128 * ROWP * 2)     // 10240
#define STAGE_BYTES (4 * TILE_BYTES)    // 40960
#define SM_TOTAL (2 * STAGE_BYTES)      // 81920

// ---------------- scratch (device globals; no allocation allowed) ----------------
__device__ __half g_doc_hi[BB * LD * DD];
__device__ __half g_doc_lo[BB * LD * DD];
__device__ __half g_q_hi[BB * LQ * DD];
__device__ __half g_q_lo[BB * LQ * DD];
__device__ float g_colsum[BB * LD];
__device__ float g_rowsum[BB * LQ];
__device__ float g_alpha[BB * LD];
__device__ float g_beta[BB * LQ];

// ---------------- helpers ----------------
#define CP_ASYNC16(dst, src) \
    asm volatile("cp.async.ca.shared.global [%0], [%1], 16;" :: "r"(dst), "l"(src) : "memory")
#define CP_COMMIT() asm volatile("cp.async.commit_group;" ::: "memory")
#define CP_WAIT(n)  asm volatile("cp.async.wait_group %0;" :: "n"(n) : "memory")

__device__ __forceinline__ uint32_t smem_u32(const void* p) {
    uint32_t a;
    asm("{ .reg .u64 t; cvta.to.shared.u64 t, %1; cvt.u32.u64 %0, t; }" : "=r"(a) : "l"(p));
    return a;
}

__device__ __forceinline__ void mma16816(float* c, const uint32_t* a, const uint32_t* b) {
    asm volatile(
        "mma.sync.aligned.m16n8k16.row.col.f32.f16.f16.f32 "
        "{%0,%1,%2,%3}, {%4,%5,%6,%7}, {%8,%9}, {%0,%1,%2,%3};"
        : "+f"(c[0]), "+f"(c[1]), "+f"(c[2]), "+f"(c[3])
        : "r"(a[0]), "r"(a[1]), "r"(a[2]), "r"(a[3]), "r"(b[0]), "r"(b[1]));
}

__device__ __forceinline__ float fast_tanh(float x) {
    float cx = fminf(fmaxf(x, -15.0f), 15.0f);
    float e = __expf(2.0f * cx);
    return __fdividef(e - 1.0f, e + 1.0f);
}

__device__ __forceinline__ uint32_t packh2(__half a, __half b) {
    __half2 p = __halves2half2(a, b);
    return *reinterpret_cast<uint32_t*>(&p);
}

// ---------------- kernel 1: zero logit accumulators ----------------
__global__ void zero_scratch_kernel() {
    int i = blockIdx.x * blockDim.x + threadIdx.x;
    if (i < BB * LD) g_colsum[i] = 0.0f;
    if (i < BB * LQ) g_rowsum[i] = 0.0f;
}

// ---------------- kernel 2: fp32 -> (hi, lo) fp16 split ----------------
#define NDOC4 (BB * LD * DD / 4)
#define NQ4   (BB * LQ * DD / 4)
__global__ __launch_bounds__(256)
void convert_kernel(const float* __restrict__ doc, const float* __restrict__ query) {
    int i = blockIdx.x * blockDim.x + threadIdx.x;
    const float4* src;
    uint2 *hip, *lop;
    int idx;
    if (i < NDOC4) {
        src = reinterpret_cast<const float4*>(doc);
        hip = reinterpret_cast<uint2*>(g_doc_hi);
        lop = reinterpret_cast<uint2*>(g_doc_lo);
        idx = i;
    } else {
        idx = i - NDOC4;
        if (idx >= NQ4) return;
        src = reinterpret_cast<const float4*>(query);
        hip = reinterpret_cast<uint2*>(g_q_hi);
        lop = reinterpret_cast<uint2*>(g_q_lo);
    }
    float4 v = src[idx];
    __half hx = __float2half_rn(v.x), hy = __float2half_rn(v.y);
    __half hz = __float2half_rn(v.z), hw = __float2half_rn(v.w);
    __half lx = __float2half_rn(v.x - __half2float(hx));
    __half ly = __float2half_rn(v.y - __half2float(hy));
    __half lz = __float2half_rn(v.z - __half2float(hz));
    __half lw = __float2half_rn(v.w - __half2float(hw));
    hip[idx] = make_uint2(packh2(hx, hy), packh2(hz, hw));
    lop[idx] = make_uint2(packh2(lx, ly), packh2(lz, lw));
}

// ---------------- kernel 3: fused fp16x3 tanh-GEMM + row/col reduction ----------------
// grid (LD/BN=16, LQ/BM=4, BB=32), block 256 (8 warps, warp grid 4m x 2n)
// NOTE: reads split operands from __device__ globals directly (device-side symbol
// addresses) -- passing them as host-side kernel args was the R5 bug.
__global__ __launch_bounds__(NTHREADS, 1)
void tanh_gemm_mma() {
    extern __shared__ char smem[];
    const uint32_t sb = smem_u32(smem);
    const int tid = threadIdx.x;
    const int wid = tid >> 5;
    const int lane = tid & 31;
    const int g = lane >> 2;     // 0..7
    const int tg = lane & 3;     // 0..3
    const int wm = wid & 3;      // 0..3 -> m offset wm*32
    const int wn = wid >> 2;     // 0..1 -> n offset wn*64

    const int b  = blockIdx.z;
    const int m0 = blockIdx.y * BM;
    const int n0 = blockIdx.x * BN;

    const __half* gsrc[4];
    gsrc[0] = g_q_hi   + ((size_t)b * LQ + m0) * DD;
    gsrc[1] = g_q_lo   + ((size_t)b * LQ + m0) * DD;
    gsrc[2] = g_doc_hi + ((size_t)b * LD + n0) * DD;
    gsrc[3] = g_doc_lo + ((size_t)b * LD + n0) * DD;

    float acc[2][8][4];
#pragma unroll
    for (int mt = 0; mt < 2; ++mt)
#pragma unroll
        for (int nt = 0; nt < 8; ++nt)
#pragma unroll
            for (int r = 0; r < 4; ++r) acc[mt][nt][r] = 0.0f;

    const int lrow = tid >> 1;          // 0..127
    const int ls0  = (tid & 1) * 2;     // segment 0 or 2

    // prefetch chunk 0
    {
        const uint32_t dbase = sb + (uint32_t)lrow * 80 + (uint32_t)ls0 * 16;
#pragma unroll
        for (int t = 0; t < 4; ++t) {
            const __half* src = gsrc[t] + (size_t)lrow * DD + ls0 * 8;
            CP_ASYNC16(dbase + t * TILE_BYTES, src);
            CP_ASYNC16(dbase + t * TILE_BYTES + 16, src + 8);
        }
        CP_COMMIT();
    }

    for (int c = 0; c < 8; ++c) {
        if (c < 7) {
            const int k0 = (c + 1) * BK;
            const uint32_t dbase = sb + ((c + 1) & 1) * STAGE_BYTES
                                 + (uint32_t)lrow * 80 + (uint32_t)ls0 * 16;
#pragma unroll
            for (int t = 0; t < 4; ++t) {
                const __half* src = gsrc[t] + (size_t)lrow * DD + k0 + ls0 * 8;
                CP_ASYNC16(dbase + t * TILE_BYTES, src);
                CP_ASYNC16(dbase + t * TILE_BYTES + 16, src + 8);
            }
            CP_COMMIT();
            CP_WAIT(1);
        } else {
            CP_WAIT(0);
        }
        __syncthreads();

        const __half* st = reinterpret_cast<const __half*>(smem + (c & 1) * STAGE_BYTES);
        const __half* Ah = st;
        const __half* Al = st + 128 * ROWP;
        const __half* Bh = st + 2 * 128 * ROWP;
        const __half* Bl = st + 3 * 128 * ROWP;

#pragma unroll
        for (int ks = 0; ks < 2; ++ks) {
            const int kc = ks * 16 + 2 * tg;
            uint32_t ahi[2][4], alo[2][4];
#pragma unroll
            for (int mt = 0; mt < 2; ++mt) {
                const int mr = wm * 32 + mt * 16 + g;
                ahi[mt][0] = *reinterpret_cast<const uint32_t*>(Ah + mr * ROWP + kc);
                ahi[mt][1] = *reinterpret_cast<const uint32_t*>(Ah + (mr + 8) * ROWP + kc);
                ahi[mt][2] = *reinterpret_cast<const uint32_t*>(Ah + mr * ROWP + kc + 8);
                ahi[mt][3] = *reinterpret_cast<const uint32_t*>(Ah + (mr + 8) * ROWP + kc + 8);
                alo[mt][0] = *reinterpret_cast<const uint32_t*>(Al + mr * ROWP + kc);
                alo[mt][1] = *reinterpret_cast<const uint32_t*>(Al + (mr + 8) * ROWP + kc);
                alo[mt][2] = *reinterpret_cast<const uint32_t*>(Al + mr * ROWP + kc + 8);
                alo[mt][3] = *reinterpret_cast<const uint32_t*>(Al + (mr + 8) * ROWP + kc + 8);
            }
#pragma unroll
            for (int nt = 0; nt < 8; ++nt) {
                const int nr = wn * 64 + nt * 8 + g;
                uint32_t bhi[2], blo[2];
                bhi[0] = *reinterpret_cast<const uint32_t*>(Bh + nr * ROWP + kc);
                bhi[1] = *reinterpret_cast<const uint32_t*>(Bh + nr * ROWP + kc + 8);
                blo[0] = *reinterpret_cast<const uint32_t*>(Bl + nr * ROWP + kc);
                blo[1] = *reinterpret_cast<const uint32_t*>(Bl + nr * ROWP + kc + 8);
#pragma unroll
                for (int mt = 0; mt < 2; ++mt) {
                    mma16816(acc[mt][nt], ahi[mt], bhi);
                    mma16816(acc[mt][nt], ahi[mt], blo);
                    mma16816(acc[mt][nt], alo[mt], bhi);
                }
            }
        }
        __syncthreads();
    }

    // ---- epilogue: tanh + row/col sums ----
    float* srow = reinterpret_cast<float*>(smem);
    float* scol = srow + 128;
    if (tid < 128) { srow[tid] = 0.0f; scol[tid] = 0.0f; }
    __syncthreads();

    float csum0[8], csum1[8];
#pragma unroll
    for (int nt = 0; nt < 8; ++nt) { csum0[nt] = 0.0f; csum1[nt] = 0.0f; }

#pragma unroll
    for (int mt = 0; mt < 2; ++mt) {
        float r0 = 0.0f, r1 = 0.0f;
#pragma unroll
        for (int nt = 0; nt < 8; ++nt) {
            float v0 = fast_tanh(acc[mt][nt][0]);
            float v1 = fast_tanh(acc[mt][nt][1]);
            float v2 = fast_tanh(acc[mt][nt][2]);
            float v3 = fast_tanh(acc[mt][nt][3]);
            r0 += v0 + v1;
            r1 += v2 + v3;
            csum0[nt] += v0 + v2;
            csum1[nt] += v1 + v3;
        }
        atomicAdd(&srow[wm * 32 + mt * 16 + g], r0);
        atomicAdd(&srow[wm * 32 + mt * 16 + g + 8], r1);
    }
#pragma unroll
    for (int nt = 0; nt < 8; ++nt) {
        atomicAdd(&scol[wn * 64 + nt * 8 + 2 * tg], csum0[nt]);
        atomicAdd(&scol[wn * 64 + nt * 8 + 2 * tg + 1], csum1[nt]);
    }
    __syncthreads();
    if (tid < 128) {
        atomicAdd(&g_rowsum[b * LQ + m0 + tid], srow[tid]);
        atomicAdd(&g_colsum[b * LD + n0 + tid], scol[tid]);
    }
}

// ---------------- kernel 4: masked softmax ----------------
__global__ __launch_bounds__(256)
void softmax_kernel(const float* __restrict__ doc_mask, const float* __restrict__ q_mask) {
    __shared__ float red[256];
    const int side = blockIdx.x;
    const int b = blockIdx.y;
    const int tid = threadIdx.x;

    const float* logits = (side == 0) ? (g_colsum + b * LD) : (g_rowsum + b * LQ);
    const float* mask   = (side == 0) ? (doc_mask + b * LD) : (q_mask + b * LQ);
    float* outw         = (side == 0) ? (g_alpha + b * LD)  : (g_beta + b * LQ);
    const int n         = (side == 0) ? LD : LQ;

    float mx = -INFINITY;
    for (int i = tid; i < n; i += 256) mx = fmaxf(mx, logits[i]);
    red[tid] = mx;
    __syncthreads();
    for (int s = 128; s > 0; s >>= 1) {
        if (tid < s) red[tid] = fmaxf(red[tid], red[tid + s]);
        __syncthreads();
    }
    mx = red[0];
    __syncthreads();

    float ssum = 0.0f;
    for (int i = tid; i < n; i += 256) {
        float e = __expf(logits[i] - mx) * mask[i];
        outw[i] = e;
        ssum += e;
    }
    red[tid] = ssum;
    __syncthreads();
    for (int s = 128; s > 0; s >>= 1) {
        if (tid < s) red[tid] += red[tid + s];
        __syncthreads();
    }
    float inv = 1.0f / red[0];
    __syncthreads();
    for (int i = tid; i < n; i += 256) outw[i] *= inv;
}

// ---------------- kernel 5: weighted pooling ----------------
#define PCHUNK 64
__global__ __launch_bounds__(256)
void pool_kernel(const float* __restrict__ doc, const float* __restrict__ query,
                 float* __restrict__ out) {
    const int chunk = blockIdx.x;   // 0..63
    const int b = blockIdx.y;
    const int d = threadIdx.x;

    const int tpc = LD / PCHUNK;    // 32
    const int qpc = LQ / PCHUNK;    // 8

    float accD = 0.0f;
    const float* dbase = doc + ((size_t)b * LD + chunk * tpc) * DD;
    const float* abase = g_alpha + b * LD + chunk * tpc;
#pragma unroll 8
    for (int t = 0; t < tpc; ++t)
        accD = fmaf(dbase[(size_t)t * DD + d], __ldg(&abase[t]), accD);

    float accQ = 0.0f;
    const float* qbase = query + ((size_t)b * LQ + chunk * qpc) * DD;
    const float* bbase = g_beta + b * LQ + chunk * qpc;
#pragma unroll 8
    for (int q = 0; q < qpc; ++q)
        accQ = fmaf(qbase[(size_t)q * DD + d], __ldg(&bbase[q]), accQ);

    atomicAdd(&out[b * (2 * DD) + d], accD);
    atomicAdd(&out[b * (2 * DD) + DD + d], accQ);
}

extern "C" void kernel_launch(void* const* d_in, const int* in_sizes, int n_in,
                              void* d_out, int out_size) {
    const float* doc      = (const float*)d_in[0];
    const float* query    = (const float*)d_in[1];
    const float* doc_mask = (const float*)d_in[2];
    const float* q_mask   = (const float*)d_in[3];
    float* out = (float*)d_out;

    cudaFuncSetAttribute(tanh_gemm_mma, cudaFuncAttributeMaxDynamicSharedMemorySize, SM_TOTAL);

    {
        int n = BB * LD;
        zero_scratch_kernel<<<(n + 1023) / 1024, 1024>>>();
    }
    cudaMemsetAsync(d_out, 0, (size_t)out_size * sizeof(float));

    {
        int total = NDOC4 + NQ4;
        convert_kernel<<<(total + 255) / 256, 256>>>(doc, query);
    }
    {
        dim3 grid(LD / BN, LQ / BM, BB);
        tanh_gemm_mma<<<grid, NTHREADS, SM_TOTAL>>>();
    }
    {
        dim3 grid(2, BB);
        softmax_kernel<<<grid, 256>>>(doc_mask, q_mask);
    }
    {
        dim3 grid(PCHUNK, BB);
        pool_kernel<<<grid, 256>>>(doc, query, out);
    }
}

// round 11
// speedup vs baseline: 1.6895x; 1.4626x over previous
#include <cuda_runtime.h>
#include <cuda_fp16.h>
#include <cstdint>
#include <math.h>

// Problem constants (crossatt_76544907149890)
#define BB 32
#define LD 2048
#define LQ 512
#define DD 256

// GEMM config
#define BM 128
#define BN 128
#define BK 32
#define NTHREADS 256
#define ROWP 40                 // padded row stride in halves (80B, conflict-free)
#define TILE_BYTES (128 * ROWP * 2)     // 10240
#define STAGE_BYTES (4 * TILE_BYTES)    // 40960
#define SM_TOTAL (2 * STAGE_BYTES)      // 81920

// ---------------- scratch (device globals; no allocation allowed) ----------------
__device__ __half g_doc_hi[BB * LD * DD];
__device__ __half g_doc_lo[BB * LD * DD];
__device__ __half g_q_hi[BB * LQ * DD];
__device__ __half g_q_lo[BB * LQ * DD];
__device__ float g_colsum[BB * LD];
__device__ float g_rowsum[BB * LQ];
__device__ float g_alpha[BB * LD];
__device__ float g_beta[BB * LQ];

// ---------------- helpers ----------------
#define CP_ASYNC16(dst, src) \
    asm volatile("cp.async.ca.shared.global [%0], [%1], 16;" :: "r"(dst), "l"(src) : "memory")
#define CP_COMMIT() asm volatile("cp.async.commit_group;" ::: "memory")
#define CP_WAIT(n)  asm volatile("cp.async.wait_group %0;" :: "n"(n) : "memory")

__device__ __forceinline__ uint32_t smem_u32(const void* p) {
    uint32_t a;
    asm("{ .reg .u64 t; cvta.to.shared.u64 t, %1; cvt.u32.u64 %0, t; }" : "=r"(a) : "l"(p));
    return a;
}

#define LDMATRIX_X4(r0, r1, r2, r3, addr)                                      \
    asm volatile("ldmatrix.sync.aligned.m8n8.x4.shared.b16 {%0,%1,%2,%3}, [%4];" \
                 : "=r"(r0), "=r"(r1), "=r"(r2), "=r"(r3) : "r"(addr))

__device__ __forceinline__ void mma16816(float* c, const uint32_t* a, const uint32_t* b) {
    asm volatile(
        "mma.sync.aligned.m16n8k16.row.col.f32.f16.f16.f32 "
        "{%0,%1,%2,%3}, {%4,%5,%6,%7}, {%8,%9}, {%0,%1,%2,%3};"
        : "+f"(c[0]), "+f"(c[1]), "+f"(c[2]), "+f"(c[3])
        : "r"(a[0]), "r"(a[1]), "r"(a[2]), "r"(a[3]), "r"(b[0]), "r"(b[1]));
}

__device__ __forceinline__ float fast_tanh(float x) {
    float cx = fminf(fmaxf(x, -15.0f), 15.0f);
    float e = __expf(2.0f * cx);
    return __fdividef(e - 1.0f, e + 1.0f);
}

__device__ __forceinline__ uint32_t packh2(__half a, __half b) {
    __half2 p = __halves2half2(a, b);
    return *reinterpret_cast<uint32_t*>(&p);
}

// ---------------- kernel 1: fp32 -> (hi, lo) fp16 split (+ zero logit scratch) ----------------
#define NDOC4 (BB * LD * DD / 4)
#define NQ4   (BB * LQ * DD / 4)
__global__ __launch_bounds__(256)
void convert_kernel(const float* __restrict__ doc, const float* __restrict__ query) {
    int i = blockIdx.x * blockDim.x + threadIdx.x;
    // fold in logit-accumulator zeroing (saves a launch)
    if (i < BB * LD) g_colsum[i] = 0.0f;
    if (i < BB * LQ) g_rowsum[i] = 0.0f;

    const float4* src;
    uint2 *hip, *lop;
    int idx;
    if (i < NDOC4) {
        src = reinterpret_cast<const float4*>(doc);
        hip = reinterpret_cast<uint2*>(g_doc_hi);
        lop = reinterpret_cast<uint2*>(g_doc_lo);
        idx = i;
    } else {
        idx = i - NDOC4;
        if (idx >= NQ4) return;
        src = reinterpret_cast<const float4*>(query);
        hip = reinterpret_cast<uint2*>(g_q_hi);
        lop = reinterpret_cast<uint2*>(g_q_lo);
    }
    float4 v = src[idx];
    __half hx = __float2half_rn(v.x), hy = __float2half_rn(v.y);
    __half hz = __float2half_rn(v.z), hw = __float2half_rn(v.w);
    __half lx = __float2half_rn(v.x - __half2float(hx));
    __half ly = __float2half_rn(v.y - __half2float(hy));
    __half lz = __float2half_rn(v.z - __half2float(hz));
    __half lw = __float2half_rn(v.w - __half2float(hw));
    hip[idx] = make_uint2(packh2(hx, hy), packh2(hz, hw));
    lop[idx] = make_uint2(packh2(lx, ly), packh2(lz, lw));
}

// ---------------- kernel 2: fused fp16x3 tanh-GEMM + row/col reduction ----------------
// grid (LD/BN=16, LQ/BM=4, BB=32), block 256 (8 warps, warp grid 4m x 2n)
__global__ __launch_bounds__(NTHREADS, 1)
void tanh_gemm_mma() {
    extern __shared__ char smem[];
    const uint32_t sb = smem_u32(smem);
    const int tid = threadIdx.x;
    const int wid = tid >> 5;
    const int lane = tid & 31;
    const int g = lane >> 2;     // 0..7
    const int tg = lane & 3;     // 0..3
    const int wm = wid & 3;      // m offset wm*32
    const int wn = wid >> 2;     // n offset wn*64

    const int b  = blockIdx.z;
    const int m0 = blockIdx.y * BM;
    const int n0 = blockIdx.x * BN;

    const __half* gsrc[4];
    gsrc[0] = g_q_hi   + ((size_t)b * LQ + m0) * DD;
    gsrc[1] = g_q_lo   + ((size_t)b * LQ + m0) * DD;
    gsrc[2] = g_doc_hi + ((size_t)b * LD + n0) * DD;
    gsrc[3] = g_doc_lo + ((size_t)b * LD + n0) * DD;

    float acc[2][8][4];
#pragma unroll
    for (int mt = 0; mt < 2; ++mt)
#pragma unroll
        for (int nt = 0; nt < 8; ++nt)
#pragma unroll
            for (int r = 0; r < 4; ++r) acc[mt][nt][r] = 0.0f;

    const int lrow = tid >> 1;          // 0..127
    const int ls0  = (tid & 1) * 2;     // segment 0 or 2

    // ldmatrix per-thread row/col offsets (in halves):
    //   row = base + (lane & 15), col = kc0 + ((lane >> 4) << 3)
    const uint32_t lm_row = (uint32_t)(lane & 15);
    const uint32_t lm_koff = (uint32_t)((lane >> 4) << 3);

    // prefetch chunk 0
    {
        const uint32_t dbase = sb + (uint32_t)lrow * 80 + (uint32_t)ls0 * 16;
#pragma unroll
        for (int t = 0; t < 4; ++t) {
            const __half* src = gsrc[t] + (size_t)lrow * DD + ls0 * 8;
            CP_ASYNC16(dbase + t * TILE_BYTES, src);
            CP_ASYNC16(dbase + t * TILE_BYTES + 16, src + 8);
        }
        CP_COMMIT();
    }

    for (int c = 0; c < 8; ++c) {
        if (c < 7) {
            const int k0 = (c + 1) * BK;
            const uint32_t dbase = sb + ((c + 1) & 1) * STAGE_BYTES
                                 + (uint32_t)lrow * 80 + (uint32_t)ls0 * 16;
#pragma unroll
            for (int t = 0; t < 4; ++t) {
                const __half* src = gsrc[t] + (size_t)lrow * DD + k0 + ls0 * 8;
                CP_ASYNC16(dbase + t * TILE_BYTES, src);
                CP_ASYNC16(dbase + t * TILE_BYTES + 16, src + 8);
            }
            CP_COMMIT();
            CP_WAIT(1);
        } else {
            CP_WAIT(0);
        }
        __syncthreads();

        const uint32_t st = sb + (c & 1) * STAGE_BYTES;
        const uint32_t Ah = st;
        const uint32_t Al = st + TILE_BYTES;
        const uint32_t Bh = st + 2 * TILE_BYTES;
        const uint32_t Bl = st + 3 * TILE_BYTES;

#pragma unroll
        for (int ks = 0; ks < 2; ++ks) {
            const uint32_t kc = (uint32_t)(ks * 16) + lm_koff;   // halves
            // ---- A fragments via ldmatrix.x4 (regs map to a0..a3) ----
            uint32_t ahi[2][4], alo[2][4];
#pragma unroll
            for (int mt = 0; mt < 2; ++mt) {
                const uint32_t ra = (uint32_t)(wm * 32 + mt * 16) + lm_row;
                const uint32_t off = ra * 80 + kc * 2;
                LDMATRIX_X4(ahi[mt][0], ahi[mt][1], ahi[mt][2], ahi[mt][3], Ah + off);
                LDMATRIX_X4(alo[mt][0], alo[mt][1], alo[mt][2], alo[mt][3], Al + off);
            }
            // ---- B fragments via ldmatrix.x4: covers nt-pair (nt, nt+1 within 16 rows) ----
            // regs: r0 = b0 of lower n8, r1 = b0 of upper n8, r2 = b1 lower, r3 = b1 upper
            uint32_t bhi[8][2], blo[8][2];
#pragma unroll
            for (int ntp = 0; ntp < 4; ++ntp) {
                const uint32_t rb = (uint32_t)(wn * 64 + ntp * 16) + lm_row;
                const uint32_t off = rb * 80 + kc * 2;
                uint32_t r0, r1, r2, r3;
                LDMATRIX_X4(r0, r1, r2, r3, Bh + off);
                bhi[2 * ntp][0] = r0; bhi[2 * ntp][1] = r2;
                bhi[2 * ntp + 1][0] = r1; bhi[2 * ntp + 1][1] = r3;
                LDMATRIX_X4(r0, r1, r2, r3, Bl + off);
                blo[2 * ntp][0] = r0; blo[2 * ntp][1] = r2;
                blo[2 * ntp + 1][0] = r1; blo[2 * ntp + 1][1] = r3;
            }
            // ---- MMAs: 3-product fp16 split ----
#pragma unroll
            for (int nt = 0; nt < 8; ++nt) {
#pragma unroll
                for (int mt = 0; mt < 2; ++mt) {
                    mma16816(acc[mt][nt], ahi[mt], bhi[nt]);
                    mma16816(acc[mt][nt], ahi[mt], blo[nt]);
                    mma16816(acc[mt][nt], alo[mt], bhi[nt]);
                }
            }
        }
        __syncthreads();
    }

    // ---- epilogue: tanh + row/col sums ----
    float* srow = reinterpret_cast<float*>(smem);
    float* scol = srow + 128;
    if (tid < 128) { srow[tid] = 0.0f; scol[tid] = 0.0f; }
    __syncthreads();

    float csum0[8], csum1[8];
#pragma unroll
    for (int nt = 0; nt < 8; ++nt) { csum0[nt] = 0.0f; csum1[nt] = 0.0f; }

#pragma unroll
    for (int mt = 0; mt < 2; ++mt) {
        float r0 = 0.0f, r1 = 0.0f;
#pragma unroll
        for (int nt = 0; nt < 8; ++nt) {
            float v0 = fast_tanh(acc[mt][nt][0]);
            float v1 = fast_tanh(acc[mt][nt][1]);
            float v2 = fast_tanh(acc[mt][nt][2]);
            float v3 = fast_tanh(acc[mt][nt][3]);
            r0 += v0 + v1;
            r1 += v2 + v3;
            csum0[nt] += v0 + v2;
            csum1[nt] += v1 + v3;
        }
        atomicAdd(&srow[wm * 32 + mt * 16 + g], r0);
        atomicAdd(&srow[wm * 32 + mt * 16 + g + 8], r1);
    }
#pragma unroll
    for (int nt = 0; nt < 8; ++nt) {
        atomicAdd(&scol[wn * 64 + nt * 8 + 2 * tg], csum0[nt]);
        atomicAdd(&scol[wn * 64 + nt * 8 + 2 * tg + 1], csum1[nt]);
    }
    __syncthreads();
    if (tid < 128) {
        atomicAdd(&g_rowsum[b * LQ + m0 + tid], srow[tid]);
        atomicAdd(&g_colsum[b * LD + n0 + tid], scol[tid]);
    }
}

// ---------------- kernel 3: masked softmax ----------------
__global__ __launch_bounds__(256)
void softmax_kernel(const float* __restrict__ doc_mask, const float* __restrict__ q_mask) {
    __shared__ float red[256];
    const int side = blockIdx.x;
    const int b = blockIdx.y;
    const int tid = threadIdx.x;

    const float* logits = (side == 0) ? (g_colsum + b * LD) : (g_rowsum + b * LQ);
    const float* mask   = (side == 0) ? (doc_mask + b * LD) : (q_mask + b * LQ);
    float* outw         = (side == 0) ? (g_alpha + b * LD)  : (g_beta + b * LQ);
    const int n         = (side == 0) ? LD : LQ;

    float mx = -INFINITY;
    for (int i = tid; i < n; i += 256) mx = fmaxf(mx, logits[i]);
    red[tid] = mx;
    __syncthreads();
    for (int s = 128; s > 0; s >>= 1) {
        if (tid < s) red[tid] = fmaxf(red[tid], red[tid + s]);
        __syncthreads();
    }
    mx = red[0];
    __syncthreads();

    float ssum = 0.0f;
    for (int i = tid; i < n; i += 256) {
        float e = __expf(logits[i] - mx) * mask[i];
        outw[i] = e;
        ssum += e;
    }
    red[tid] = ssum;
    __syncthreads();
    for (int s = 128; s > 0; s >>= 1) {
        if (tid < s) red[tid] += red[tid + s];
        __syncthreads();
    }
    float inv = 1.0f / red[0];
    __syncthreads();
    for (int i = tid; i < n; i += 256) outw[i] *= inv;
}

// ---------------- kernel 4: weighted pooling ----------------
#define PCHUNK 64
__global__ __launch_bounds__(256)
void pool_kernel(const float* __restrict__ doc, const float* __restrict__ query,
                 float* __restrict__ out) {
    const int chunk = blockIdx.x;   // 0..63
    const int b = blockIdx.y;
    const int d = threadIdx.x;

    const int tpc = LD / PCHUNK;    // 32
    const int qpc = LQ / PCHUNK;    // 8

    float accD = 0.0f;
    const float* dbase = doc + ((size_t)b * LD + chunk * tpc) * DD;
    const float* abase = g_alpha + b * LD + chunk * tpc;
#pragma unroll 8
    for (int t = 0; t < tpc; ++t)
        accD = fmaf(dbase[(size_t)t * DD + d], __ldg(&abase[t]), accD);

    float accQ = 0.0f;
    const float* qbase = query + ((size_t)b * LQ + chunk * qpc) * DD;
    const float* bbase = g_beta + b * LQ + chunk * qpc;
#pragma unroll 8
    for (int q = 0; q < qpc; ++q)
        accQ = fmaf(qbase[(size_t)q * DD + d], __ldg(&bbase[q]), accQ);

    atomicAdd(&out[b * (2 * DD) + d], accD);
    atomicAdd(&out[b * (2 * DD) + DD + d], accQ);
}

extern "C" void kernel_launch(void* const* d_in, const int* in_sizes, int n_in,
                              void* d_out, int out_size) {
    const float* doc      = (const float*)d_in[0];
    const float* query    = (const float*)d_in[1];
    const float* doc_mask = (const float*)d_in[2];
    const float* q_mask   = (const float*)d_in[3];
    float* out = (float*)d_out;

    cudaFuncSetAttribute(tanh_gemm_mma, cudaFuncAttributeMaxDynamicSharedMemorySize, SM_TOTAL);

    cudaMemsetAsync(d_out, 0, (size_t)out_size * sizeof(float));
    {
        int total = NDOC4 + NQ4;
        convert_kernel<<<(total + 255) / 256, 256>>>(doc, query);
    }
    {
        dim3 grid(LD / BN, LQ / BM, BB);
        tanh_gemm_mma<<<grid, NTHREADS, SM_TOTAL>>>();
    }
    {
        dim3 grid(2, BB);
        softmax_kernel<<<grid, 256>>>(doc_mask, q_mask);
    }
    {
        dim3 grid(PCHUNK, BB);
        pool_kernel<<<grid, 256>>>(doc, query, out);
    }
}